// round 1
// baseline (speedup 1.0000x reference)
#include <cuda_runtime.h>
#include <cstdint>

// Problem constants (fixed shapes from reference setup_inputs)
#define Sn 2
#define Bn 16
#define Kn 128
#define Hd 128
#define Wd 128
#define HWn (Hd*Wd)

#define EPSf 1e-6f
#define MAXD 181.01933598375618f      // sqrt(128^2+128^2)
#define MAXD2 32768.0f
#define MPD (MAXD + EPSf)

// ---- device scratch (no allocation allowed) ----
static __device__ float4 g_pq[Bn * HWn];            // per (b,cell): {p0, p1, q0, q1}, q = (M+eps) - p*M
static __device__ float4 g_t1[Bn * Hd];             // per (b,row): {sum p0*dmin, sum p1*dmin, sum p0, sum p1}
static __device__ float  g_part[Sn * Bn * Kn * Hd]; // ((s*Bn+b)*Kn+slot)*Hd + row : partial sums of x^-9

__device__ __forceinline__ float sqrt_ap(float x) {
    float r; asm("sqrt.approx.f32 %0, %1;" : "=f"(r) : "f"(x)); return r;
}
__device__ __forceinline__ float rcp_ap(float x) {
    float r; asm("rcp.approx.f32 %0, %1;" : "=f"(r) : "f"(x)); return r;
}

// ============================================================================
// Pass A: sigmoid precompute (p,q), dmin per cell, term1 row partials
// grid: (row=128, b=16), block: 128 threads (= x, and = k for compaction)
// ============================================================================
__global__ void __launch_bounds__(128) passA_kernel(
    const float* __restrict__ hm, const int* __restrict__ ctr,
    const int* __restrict__ mask)
{
    const int row = blockIdx.x, b = blockIdx.y;
    const int tid = threadIdx.x;
    const int wid = tid >> 5, lid = tid & 31;

    __shared__ float spx[Kn], sdy2[Kn];
    __shared__ int   wcnt[4];
    __shared__ float red[4][4];

    const float fy = (float)row, fx = (float)tid;

    // --- compaction of valid points (thread = k) ---
    const int k = tid;
    const int mk = mask[b * Kn + k];
    unsigned bal = __ballot_sync(0xFFFFFFFFu, mk != 0);
    if (lid == 0) wcnt[wid] = __popc(bal);

    // --- sigmoid / q precompute for this cell (both s) ---
    const int base = b * HWn + row * Wd + tid;
    float h0 = hm[base];
    float h1 = hm[Bn * HWn + base];
    float p0 = 1.0f / (1.0f + __expf(-h0));
    float p1 = 1.0f / (1.0f + __expf(-h1));
    p0 = fminf(fmaxf(p0, 1e-4f), 1.0f - 1e-4f);
    p1 = fminf(fmaxf(p1, 1e-4f), 1.0f - 1e-4f);
    float q0 = MPD - p0 * MAXD;
    float q1 = MPD - p1 * MAXD;
    g_pq[base] = make_float4(p0, p1, q0, q1);

    __syncthreads();
    int off = 0;
#pragma unroll
    for (int i = 0; i < 4; i++) if (i < wid) off += wcnt[i];
    const int V = wcnt[0] + wcnt[1] + wcnt[2] + wcnt[3];

    if (mk) {
        int slot = off + __popc(bal & ((1u << lid) - 1u));
        // pts = ctr[..., ::-1] : py = ctr[...,1], px = ctr[...,0]
        float pxk = (float)ctr[(b * Kn + k) * 2 + 0];
        float pyk = (float)ctr[(b * Kn + k) * 2 + 1];
        spx[slot] = pxk;
        float dyv = fy - pyk;
        sdy2[slot] = dyv * dyv;
    }
    __syncthreads();

    // --- masked min over valid points (squared distances; sqrt once) ---
    float mind = MAXD2;
#pragma unroll 4
    for (int j = 0; j < V; j++) {
        float dxv = fx - spx[j];
        mind = fminf(mind, fmaf(dxv, dxv, sdy2[j]));
    }
    float dmin = sqrt_ap(mind);

    // --- block-reduce 4 accumulators for term1 ---
    float v0 = p0 * dmin, v1 = p1 * dmin, v2 = p0, v3 = p1;
#pragma unroll
    for (int o = 16; o > 0; o >>= 1) {
        v0 += __shfl_down_sync(0xFFFFFFFFu, v0, o);
        v1 += __shfl_down_sync(0xFFFFFFFFu, v1, o);
        v2 += __shfl_down_sync(0xFFFFFFFFu, v2, o);
        v3 += __shfl_down_sync(0xFFFFFFFFu, v3, o);
    }
    if (lid == 0) { red[wid][0] = v0; red[wid][1] = v1; red[wid][2] = v2; red[wid][3] = v3; }
    __syncthreads();
    if (tid == 0) {
        float4 o4;
        o4.x = red[0][0] + red[1][0] + red[2][0] + red[3][0];
        o4.y = red[0][1] + red[1][1] + red[2][1] + red[3][1];
        o4.z = red[0][2] + red[1][2] + red[2][2] + red[3][2];
        o4.w = red[0][3] + red[1][3] + red[2][3] + red[3][3];
        g_t1[b * Hd + row] = o4;
    }
}

// ============================================================================
// Pass B: heavy term2 partials. thread = compacted valid point, loops one row.
// grid: (row=128, b=16), block: 128 threads
// ============================================================================
__global__ void __launch_bounds__(128) passB_kernel(
    const int* __restrict__ ctr, const int* __restrict__ mask)
{
    const int row = blockIdx.x, b = blockIdx.y;
    const int tid = threadIdx.x;
    const int wid = tid >> 5, lid = tid & 31;

    __shared__ float4 spq[Wd];
    __shared__ float  spx[Kn], spy[Kn];
    __shared__ int    wcnt[4];

    spq[tid] = g_pq[b * HWn + row * Wd + tid];

    const int mk = mask[b * Kn + tid];
    unsigned bal = __ballot_sync(0xFFFFFFFFu, mk != 0);
    if (lid == 0) wcnt[wid] = __popc(bal);
    __syncthreads();
    int off = 0;
#pragma unroll
    for (int i = 0; i < 4; i++) if (i < wid) off += wcnt[i];
    const int V = wcnt[0] + wcnt[1] + wcnt[2] + wcnt[3];
    if (mk) {
        int slot = off + __popc(bal & ((1u << lid) - 1u));
        spx[slot] = (float)ctr[(b * Kn + tid) * 2 + 0];
        spy[slot] = (float)ctr[(b * Kn + tid) * 2 + 1];
    }
    __syncthreads();

    if (tid < V) {
        const float px = spx[tid];
        const float py = spy[tid];
        const float fy = (float)row;
        const float dyv = fy - py;
        const float dy2 = dyv * dyv;
        float acc0 = 0.0f, acc1 = 0.0f;
        float u = -px;
#pragma unroll 4
        for (int xi = 0; xi < Wd; xi++) {
            float4 pq = spq[xi];                  // broadcast LDS.128
            float dsq = fmaf(u, u, dy2);
            float d = sqrt_ap(dsq);
            float x0 = fmaf(pq.x, d, pq.z);       // (1-p0)M + p0 d + eps
            float x1 = fmaf(pq.y, d, pq.w);
            float pr = x0 * x1;
            float r = rcp_ap(pr);                 // batched reciprocal for both s
            float i0 = r * x1;
            float i1 = r * x0;
            float a0 = i0 * i0; a0 = a0 * a0; a0 = a0 * a0;   // i0^8
            float a1 = i1 * i1; a1 = a1 * a1; a1 = a1 * a1;
            acc0 = fmaf(a0, i0, acc0);            // += i0^9  (i.e. x0^-9)
            acc1 = fmaf(a1, i1, acc1);
            u += 1.0f;
        }
        g_part[((0 * Bn + b) * Kn + tid) * Hd + row] = acc0;
        g_part[((1 * Bn + b) * Kn + tid) * Hd + row] = acc1;
    }
}

// ============================================================================
// Pass C: finalize — minn, term1/term2 combine, bounded IoU, final scalars
// single block, 256 threads
// ============================================================================
__device__ __forceinline__ float smoothl(float l) {
    return (l < 0.2f) ? (2.5f * l * l) : (l - 0.1f);
}

__global__ void __launch_bounds__(256) passC_kernel(
    const float* __restrict__ wh_map, const float* __restrict__ reg_map,
    const float* __restrict__ reg_gt, const float* __restrict__ wh_gt,
    const int* __restrict__ ind, const int* __restrict__ mask,
    float* __restrict__ out, int out_size)
{
    const int tid = threadIdx.x;
    __shared__ float sval[Sn * Bn * Kn];      // 4096 floats (reused)
    __shared__ int   smsum[Bn];
    __shared__ float sterm_hm[Sn * Bn], sterm_iou[Sn * Bn];

    // phase 1: valid counts per b
    if (tid < Bn) {
        int s = 0;
        for (int k = 0; k < Kn; k++) s += (mask[tid * Kn + k] != 0) ? 1 : 0;
        smsum[tid] = s;
    }
    __syncthreads();

    // phase 2: minn per (s,b,slot)
    for (int t = tid; t < Sn * Bn * Kn; t += 256) {
        int slot = t & (Kn - 1);
        int sb = t / Kn;
        int b = sb & (Bn - 1);
        float v = 0.0f;
        if (slot < smsum[b]) {
            const float* pp = &g_part[t * Hd];
            float sum = 0.0f;
#pragma unroll 4
            for (int r = 0; r < Hd; r++) sum += pp[r];
            v = powf(sum * (1.0f / (float)HWn), -1.0f / 9.0f);
        }
        sval[t] = v;
    }
    __syncthreads();

    // phase 3: hm term per (s,b)
    if (tid < Sn * Bn) {
        int s = tid / Bn, b = tid & (Bn - 1);
        float t2 = 0.0f;
        for (int j = 0; j < Kn; j++) t2 += sval[tid * Kn + j];
        t2 /= fmaxf((float)smsum[b], 1.0f);
        float num = 0.0f, nden = 0.0f;
        for (int r = 0; r < Hd; r++) {
            float4 v = g_t1[b * Hd + r];
            num  += (s == 0) ? v.x : v.y;
            nden += (s == 0) ? v.z : v.w;
        }
        float t1 = num / (nden + EPSf);
        float validb = (smsum[b] > 0) ? 1.0f : 0.0f;
        sterm_hm[tid] = (t1 + t2) * validb;
    }
    __syncthreads();

    // phase 4: bounded IoU per (s,b,k) -> reuse sval
    for (int t = tid; t < Sn * Bn * Kn; t += 256) {
        int k = t & (Kn - 1);
        int sb = t / Kn;
        int b = sb & (Bn - 1);
        float v = 0.0f;
        if (mask[b * Kn + k] != 0) {
            int id = ind[b * Kn + k];
            float R0 = reg_map[(sb * 2 + 0) * HWn + id];
            float R1 = reg_map[(sb * 2 + 1) * HWn + id];
            float W0 = wh_map[(sb * 2 + 0) * HWn + id];
            float W1 = wh_map[(sb * 2 + 1) * HWn + id];
            float g0 = reg_gt[(b * Kn + k) * 2 + 0];
            float g1 = reg_gt[(b * Kn + k) * 2 + 1];
            float wg = wh_gt[(b * Kn + k) * 2 + 0];
            float hg = wh_gt[(b * Kn + k) * 2 + 1];
            float adx = fabsf(g0 - R0);
            float ady = fabsf(g1 - R1);
            float ldx = 1.0f - fmaxf((wg - 2.0f * adx) / (wg + 2.0f * adx + EPSf), 0.0f);
            float ldy = 1.0f - fmaxf((hg - 2.0f * ady) / (hg + 2.0f * ady + EPSf), 0.0f);
            float ldw = 1.0f - fminf(wg / (W0 + EPSf), W0 / (wg + EPSf));
            float ldh = 1.0f - fminf(hg / (W1 + EPSf), W1 / (hg + EPSf));
            v = smoothl(ldx) + smoothl(ldy) + smoothl(ldw) + smoothl(ldh);
        }
        sval[t] = v;
    }
    __syncthreads();

    if (tid < Sn * Bn) {
        int b = tid & (Bn - 1);
        float num = 0.0f;
        for (int j = 0; j < Kn; j++) num += sval[tid * Kn + j];
        float den = fmaxf((float)smsum[b], 1.0f) * 4.0f;
        float validb = (smsum[b] > 0) ? 1.0f : 0.0f;
        sterm_iou[tid] = (num / den) * validb;
    }
    __syncthreads();

    if (tid == 0) {
        float hm_loss = 0.0f, iou_loss = 0.0f;
        for (int i = 0; i < Sn * Bn; i++) { hm_loss += sterm_hm[i]; iou_loss += sterm_iou[i]; }
        hm_loss *= (1.0f / (float)(Sn * Bn));
        iou_loss *= (1.0f / (float)(Sn * Bn));
        float loss = 1.0f * hm_loss + 0.1f * iou_loss;
        out[0] = loss;
        if (out_size > 1) out[1] = hm_loss;
        if (out_size > 2) out[2] = iou_loss;
    }
}

// ============================================================================
extern "C" void kernel_launch(void* const* d_in, const int* in_sizes, int n_in,
                              void* d_out, int out_size)
{
    const float* hm      = (const float*)d_in[0];
    const float* wh_map  = (const float*)d_in[1];
    const float* reg_map = (const float*)d_in[2];
    const float* reg_gt  = (const float*)d_in[3];
    const float* wh_gt   = (const float*)d_in[4];
    const int*   ind     = (const int*)d_in[5];
    const int*   ctr     = (const int*)d_in[6];
    const int*   mask    = (const int*)d_in[7];
    float* out = (float*)d_out;

    dim3 grid(Hd, Bn);
    passA_kernel<<<grid, 128>>>(hm, ctr, mask);
    passB_kernel<<<grid, 128>>>(ctr, mask);
    passC_kernel<<<1, 256>>>(wh_map, reg_map, reg_gt, wh_gt, ind, mask, out, out_size);
}

// round 3
// speedup vs baseline: 3.2695x; 3.2695x over previous
#include <cuda_runtime.h>
#include <cstdint>

// Problem constants (fixed shapes from reference setup_inputs)
#define Sn 2
#define Bn 16
#define Kn 128
#define Hd 128
#define Wd 128
#define HWn (Hd*Wd)

#define EPSf 1e-6f
#define MAXD 181.01933598375618f      // sqrt(128^2+128^2)
#define MAXD2 32768.0f
#define MPD (MAXD + EPSf)

typedef unsigned long long ull;

// ---- device scratch (no allocation allowed) ----
static __device__ float4 g_t1[Bn * Hd];                  // per (b,row): {sum p0*dmin, sum p1*dmin, sum p0, sum p1}
static __device__ float  g_part2[Sn * Bn * 256 * Kn];    // ((sb)*256 + row*2+half)*Kn + slot
static __device__ float  g_minn[Sn * Bn * Kn];           // per (s,b,slot): minn (0 for invalid)

__device__ __forceinline__ float sqrt_ap(float x) {
    float r; asm("sqrt.approx.f32 %0, %1;" : "=f"(r) : "f"(x)); return r;
}
__device__ __forceinline__ float rcp_ap(float x) {
    float r; asm("rcp.approx.f32 %0, %1;" : "=f"(r) : "f"(x)); return r;
}
__device__ __forceinline__ ull pk(float lo, float hi) {
    ull r; asm("mov.b64 %0, {%1, %2};" : "=l"(r) : "f"(lo), "f"(hi)); return r;
}
__device__ __forceinline__ void upk(float& lo, float& hi, ull v) {
    asm("mov.b64 {%0, %1}, %2;" : "=f"(lo), "=f"(hi) : "l"(v));
}
__device__ __forceinline__ ull mul2(ull a, ull b) {
    ull r; asm("mul.rn.f32x2 %0, %1, %2;" : "=l"(r) : "l"(a), "l"(b)); return r;
}
__device__ __forceinline__ ull fma2(ull a, ull b, ull c) {
    ull r; asm("fma.rn.f32x2 %0, %1, %2, %3;" : "=l"(r) : "l"(a), "l"(b), "l"(c)); return r;
}

// ============================================================================
// Pass A: dmin per cell + term1 row partials (own sigmoid, no scratch deps)
// grid: (row=128, b=16), block: 128 threads
// ============================================================================
__global__ void __launch_bounds__(128) passA_kernel(
    const float* __restrict__ hm, const int* __restrict__ ctr,
    const int* __restrict__ mask)
{
    const int row = blockIdx.x, b = blockIdx.y;
    const int tid = threadIdx.x;
    const int wid = tid >> 5, lid = tid & 31;

    __shared__ float spx[Kn], sdy2[Kn];
    __shared__ int   wcnt[4];
    __shared__ float red[4][4];

    const float fy = (float)row, fx = (float)tid;

    // --- compaction of valid points (thread = k) ---
    const int mk = mask[b * Kn + tid];
    unsigned bal = __ballot_sync(0xFFFFFFFFu, mk != 0);
    if (lid == 0) wcnt[wid] = __popc(bal);

    // --- sigmoid for this cell (both s) ---
    const int base = b * HWn + row * Wd + tid;
    float h0 = hm[base];
    float h1 = hm[Bn * HWn + base];
    float p0 = 1.0f / (1.0f + __expf(-h0));
    float p1 = 1.0f / (1.0f + __expf(-h1));
    p0 = fminf(fmaxf(p0, 1e-4f), 1.0f - 1e-4f);
    p1 = fminf(fmaxf(p1, 1e-4f), 1.0f - 1e-4f);

    __syncthreads();
    int off = 0;
#pragma unroll
    for (int i = 0; i < 4; i++) if (i < wid) off += wcnt[i];
    const int V = wcnt[0] + wcnt[1] + wcnt[2] + wcnt[3];

    if (mk) {
        int slot = off + __popc(bal & ((1u << lid) - 1u));
        // pts = ctr[..., ::-1] : py = ctr[...,1], px = ctr[...,0]
        float pxk = (float)ctr[(b * Kn + tid) * 2 + 0];
        float pyk = (float)ctr[(b * Kn + tid) * 2 + 1];
        spx[slot] = pxk;
        float dyv = fy - pyk;
        sdy2[slot] = dyv * dyv;
    }
    __syncthreads();

    // --- masked min over valid points (squared distances; sqrt once) ---
    float mind = MAXD2;
#pragma unroll 4
    for (int j = 0; j < V; j++) {
        float dxv = fx - spx[j];
        mind = fminf(mind, fmaf(dxv, dxv, sdy2[j]));
    }
    float dmin = sqrt_ap(mind);

    // --- block-reduce 4 accumulators for term1 ---
    float v0 = p0 * dmin, v1 = p1 * dmin, v2 = p0, v3 = p1;
#pragma unroll
    for (int o = 16; o > 0; o >>= 1) {
        v0 += __shfl_down_sync(0xFFFFFFFFu, v0, o);
        v1 += __shfl_down_sync(0xFFFFFFFFu, v1, o);
        v2 += __shfl_down_sync(0xFFFFFFFFu, v2, o);
        v3 += __shfl_down_sync(0xFFFFFFFFu, v3, o);
    }
    if (lid == 0) { red[wid][0] = v0; red[wid][1] = v1; red[wid][2] = v2; red[wid][3] = v3; }
    __syncthreads();
    if (tid == 0) {
        float4 o4;
        o4.x = red[0][0] + red[1][0] + red[2][0] + red[3][0];
        o4.y = red[0][1] + red[1][1] + red[2][1] + red[3][1];
        o4.z = red[0][2] + red[1][2] + red[2][2] + red[3][2];
        o4.w = red[0][3] + red[1][3] + red[2][3] + red[3][3];
        g_t1[b * Hd + row] = o4;
    }
}

// ============================================================================
// Pass B: heavy term2 partials. Work item = (valid slot, half row of x).
// All 128 threads busy when V>=64. f32x2-packed pow chain, 4-wide batched rcp.
// grid: (row=128, b=16), block: 128 threads
// ============================================================================
__global__ void __launch_bounds__(128) passB_kernel(
    const float* __restrict__ hm, const int* __restrict__ ctr,
    const int* __restrict__ mask)
{
    const int row = blockIdx.x, b = blockIdx.y;
    const int tid = threadIdx.x;
    const int wid = tid >> 5, lid = tid & 31;

    __shared__ float4 spq[Wd];
    __shared__ float  spx[Kn], spy[Kn];
    __shared__ int    wcnt[4];

    // --- fused sigmoid: p,q for this row's cells (both s) ---
    const int base = b * HWn + row * Wd + tid;
    float h0 = hm[base];
    float h1 = hm[Bn * HWn + base];
    float p0 = 1.0f / (1.0f + __expf(-h0));
    float p1 = 1.0f / (1.0f + __expf(-h1));
    p0 = fminf(fmaxf(p0, 1e-4f), 1.0f - 1e-4f);
    p1 = fminf(fmaxf(p1, 1e-4f), 1.0f - 1e-4f);
    spq[tid] = make_float4(p0, p1, MPD - p0 * MAXD, MPD - p1 * MAXD);

    // --- compaction ---
    const int mk = mask[b * Kn + tid];
    unsigned bal = __ballot_sync(0xFFFFFFFFu, mk != 0);
    if (lid == 0) wcnt[wid] = __popc(bal);
    __syncthreads();
    int off = 0;
#pragma unroll
    for (int i = 0; i < 4; i++) if (i < wid) off += wcnt[i];
    const int V = wcnt[0] + wcnt[1] + wcnt[2] + wcnt[3];
    if (mk) {
        int slot = off + __popc(bal & ((1u << lid) - 1u));
        spx[slot] = (float)ctr[(b * Kn + tid) * 2 + 0];
        spy[slot] = (float)ctr[(b * Kn + tid) * 2 + 1];
    }
    __syncthreads();

    const float fy = (float)row;

    for (int w = tid; w < 2 * Kn; w += 128) {
        const int slot = w >> 1, half = w & 1;
        ull acc = 0ULL;
        if (slot < V) {
            const float px = spx[slot];
            const float py = spy[slot];
            const float dyv = fy - py;
            const float dy2 = dyv * dyv;
            const int xb = half << 6;
            const float u0 = (float)xb - px;
#pragma unroll 4
            for (int g = 0; g < 16; g++) {
                const float ug = u0 + (float)(g * 4);
                float P[4]; ull xv[4];
#pragma unroll
                for (int j = 0; j < 4; j++) {
                    float t = ug + (float)j;
                    float dsq = fmaf(t, t, dy2);
                    float d = sqrt_ap(dsq);
                    float4 pq = spq[xb + g * 4 + j];     // broadcast LDS.128
                    float x0 = fmaf(pq.x, d, pq.z);      // (1-p0)M + p0 d + eps
                    float x1 = fmaf(pq.y, d, pq.w);
                    xv[j] = pk(x0, x1);
                    P[j] = x0 * x1;
                }
                // one rcp for 8 values: r = 1/(P0 P1 P2 P3)
                float P01 = P[0] * P[1];
                float P23 = P[2] * P[3];
                float r = rcp_ap(P01 * P23);
                float r01 = r * P23;                     // 1/(P0 P1)
                float r23 = r * P01;                     // 1/(P2 P3)
                float qv[4];
                qv[0] = r01 * P[1];                      // 1/P0
                qv[1] = r01 * P[0];
                qv[2] = r23 * P[3];
                qv[3] = r23 * P[2];
#pragma unroll
                for (int j = 0; j < 4; j++) {
                    float x0, x1; upk(x0, x1, xv[j]);
                    float i0 = qv[j] * x1;               // 1/x0
                    float i1 = qv[j] * x0;               // 1/x1
                    ull iv = pk(i0, i1);
                    ull a = mul2(iv, iv);                // i^2
                    a = mul2(a, a);                      // i^4
                    a = mul2(a, a);                      // i^8
                    acc = fma2(a, iv, acc);              // += i^9 = x^-9
                }
            }
        }
        float a0, a1; upk(a0, a1, acc);
        const int rr = row * 2 + half;
        g_part2[((0 * Bn + b) * 256 + rr) * Kn + slot] = a0;
        g_part2[((1 * Bn + b) * 256 + rr) * Kn + slot] = a1;
    }
}

// ============================================================================
// Pass C1: reduce g_part2 over 256 row-halves -> minn per (s,b,slot)
// grid: 512 blocks x 256 threads; warp per (s,b,slot)
// ============================================================================
__global__ void __launch_bounds__(256) passC1_kernel(const int* __restrict__ mask)
{
    const int warpid = threadIdx.x >> 5, lane = threadIdx.x & 31;
    const int sb = blockIdx.x >> 4;                 // 0..31 (s*Bn+b)
    const int b = sb & (Bn - 1);
    const int slot = ((blockIdx.x & 15) << 3) + warpid;

    __shared__ int wcnt[4];
    if (threadIdx.x < Kn) {
        int mk = mask[b * Kn + threadIdx.x];
        unsigned bal = __ballot_sync(0xFFFFFFFFu, mk != 0);
        if ((threadIdx.x & 31) == 0) wcnt[threadIdx.x >> 5] = __popc(bal);
    }
    __syncthreads();
    const int V = wcnt[0] + wcnt[1] + wcnt[2] + wcnt[3];

    float v = 0.0f;
    if (slot < V) {
        const float* bp = &g_part2[(sb * 256 + lane) * Kn + slot];
        float s = 0.0f;
#pragma unroll
        for (int t = 0; t < 8; t++) s += bp[t * 32 * Kn];
#pragma unroll
        for (int o = 16; o > 0; o >>= 1) s += __shfl_down_sync(0xFFFFFFFFu, s, o);
        if (lane == 0) v = powf(s * (1.0f / (float)HWn), -1.0f / 9.0f);
    }
    if (lane == 0) g_minn[sb * Kn + slot] = v;
}

// ============================================================================
// Pass C2: finalize — term1/term2 combine, bounded IoU, final scalars
// single block, 256 threads
// ============================================================================
__device__ __forceinline__ float smoothl(float l) {
    return (l < 0.2f) ? (2.5f * l * l) : (l - 0.1f);
}

__global__ void __launch_bounds__(256) passC2_kernel(
    const float* __restrict__ wh_map, const float* __restrict__ reg_map,
    const float* __restrict__ reg_gt, const float* __restrict__ wh_gt,
    const int* __restrict__ ind, const int* __restrict__ mask,
    float* __restrict__ out, int out_size)
{
    const int tid = threadIdx.x;
    __shared__ float sval[Sn * Bn * Kn];      // 4096 floats
    __shared__ int   smsum[Bn];
    __shared__ float sterm_hm[Sn * Bn], sterm_iou[Sn * Bn];

    // valid counts per b
    if (tid < Bn) {
        int s = 0;
        for (int k = 0; k < Kn; k++) s += (mask[tid * Kn + k] != 0) ? 1 : 0;
        smsum[tid] = s;
    }
    __syncthreads();

    // hm term per (s,b)
    if (tid < Sn * Bn) {
        int s = tid / Bn, b = tid & (Bn - 1);
        float t2 = 0.0f;
        for (int j = 0; j < Kn; j++) t2 += g_minn[tid * Kn + j];
        t2 /= fmaxf((float)smsum[b], 1.0f);
        float num = 0.0f, nden = 0.0f;
        for (int r = 0; r < Hd; r++) {
            float4 v = g_t1[b * Hd + r];
            num  += (s == 0) ? v.x : v.y;
            nden += (s == 0) ? v.z : v.w;
        }
        float t1 = num / (nden + EPSf);
        float validb = (smsum[b] > 0) ? 1.0f : 0.0f;
        sterm_hm[tid] = (t1 + t2) * validb;
    }

    // bounded IoU per (s,b,k)
    for (int t = tid; t < Sn * Bn * Kn; t += 256) {
        int k = t & (Kn - 1);
        int sb = t / Kn;
        int b = sb & (Bn - 1);
        float v = 0.0f;
        if (mask[b * Kn + k] != 0) {
            int id = ind[b * Kn + k];
            float R0 = reg_map[(sb * 2 + 0) * HWn + id];
            float R1 = reg_map[(sb * 2 + 1) * HWn + id];
            float W0 = wh_map[(sb * 2 + 0) * HWn + id];
            float W1 = wh_map[(sb * 2 + 1) * HWn + id];
            float g0 = reg_gt[(b * Kn + k) * 2 + 0];
            float g1 = reg_gt[(b * Kn + k) * 2 + 1];
            float wg = wh_gt[(b * Kn + k) * 2 + 0];
            float hg = wh_gt[(b * Kn + k) * 2 + 1];
            float adx = fabsf(g0 - R0);
            float ady = fabsf(g1 - R1);
            float ldx = 1.0f - fmaxf((wg - 2.0f * adx) / (wg + 2.0f * adx + EPSf), 0.0f);
            float ldy = 1.0f - fmaxf((hg - 2.0f * ady) / (hg + 2.0f * ady + EPSf), 0.0f);
            float ldw = 1.0f - fminf(wg / (W0 + EPSf), W0 / (wg + EPSf));
            float ldh = 1.0f - fminf(hg / (W1 + EPSf), W1 / (hg + EPSf));
            v = smoothl(ldx) + smoothl(ldy) + smoothl(ldw) + smoothl(ldh);
        }
        sval[t] = v;
    }
    __syncthreads();

    if (tid < Sn * Bn) {
        int b = tid & (Bn - 1);
        float num = 0.0f;
        for (int j = 0; j < Kn; j++) num += sval[tid * Kn + j];
        float den = fmaxf((float)smsum[b], 1.0f) * 4.0f;
        float validb = (smsum[b] > 0) ? 1.0f : 0.0f;
        sterm_iou[tid] = (num / den) * validb;
    }
    __syncthreads();

    if (tid == 0) {
        float hm_loss = 0.0f, iou_loss = 0.0f;
        for (int i = 0; i < Sn * Bn; i++) { hm_loss += sterm_hm[i]; iou_loss += sterm_iou[i]; }
        hm_loss *= (1.0f / (float)(Sn * Bn));
        iou_loss *= (1.0f / (float)(Sn * Bn));
        float loss = 1.0f * hm_loss + 0.1f * iou_loss;
        out[0] = loss;
        if (out_size > 1) out[1] = hm_loss;
        if (out_size > 2) out[2] = iou_loss;
    }
}

// ============================================================================
extern "C" void kernel_launch(void* const* d_in, const int* in_sizes, int n_in,
                              void* d_out, int out_size)
{
    const float* hm      = (const float*)d_in[0];
    const float* wh_map  = (const float*)d_in[1];
    const float* reg_map = (const float*)d_in[2];
    const float* reg_gt  = (const float*)d_in[3];
    const float* wh_gt   = (const float*)d_in[4];
    const int*   ind     = (const int*)d_in[5];
    const int*   ctr     = (const int*)d_in[6];
    const int*   mask    = (const int*)d_in[7];
    float* out = (float*)d_out;

    dim3 grid(Hd, Bn);
    passA_kernel<<<grid, 128>>>(hm, ctr, mask);
    passB_kernel<<<grid, 128>>>(hm, ctr, mask);
    passC1_kernel<<<512, 256>>>(mask);
    passC2_kernel<<<1, 256>>>(wh_map, reg_map, reg_gt, wh_gt, ind, mask, out, out_size);
}

// round 4
// speedup vs baseline: 5.8156x; 1.7788x over previous
#include <cuda_runtime.h>
#include <cstdint>

#define Sn 2
#define Bn 16
#define Kn 128
#define Hd 128
#define Wd 128
#define HWn (Hd*Wd)

#define EPSf 1e-6f
#define MAXD 181.01933598375618f
#define MAXD2 32768.0f
#define MPD (MAXD + EPSf)

typedef unsigned long long ull;

// ---- device scratch ----
static __device__ float4 g_t1[Bn * Hd];                  // per (b,row): {sum p0*dmin, sum p1*dmin, sum p0, sum p1}
static __device__ float  g_part2[Sn * Bn * 256 * Kn];    // ((sb)*256 + row*2+half)*Kn + slot
static __device__ float  g_minn[Sn * Bn * Kn];           // per (s,b,slot)
static __device__ float  g_iou[Sn * Bn];                 // per (s,b): sum of smooth-l
static __device__ int    g_msum[Bn];                     // per b: valid count

__device__ __forceinline__ float sqrt_ap(float x) {
    float r; asm("sqrt.approx.f32 %0, %1;" : "=f"(r) : "f"(x)); return r;
}
__device__ __forceinline__ float rcp_ap(float x) {
    float r; asm("rcp.approx.f32 %0, %1;" : "=f"(r) : "f"(x)); return r;
}
__device__ __forceinline__ ull pk(float lo, float hi) {
    ull r; asm("mov.b64 %0, {%1, %2};" : "=l"(r) : "f"(lo), "f"(hi)); return r;
}
__device__ __forceinline__ void upk(float& lo, float& hi, ull v) {
    asm("mov.b64 {%0, %1}, %2;" : "=f"(lo), "=f"(hi) : "l"(v));
}
__device__ __forceinline__ ull mul2(ull a, ull b) {
    ull r; asm("mul.rn.f32x2 %0, %1, %2;" : "=l"(r) : "l"(a), "l"(b)); return r;
}
__device__ __forceinline__ ull fma2(ull a, ull b, ull c) {
    ull r; asm("fma.rn.f32x2 %0, %1, %2, %3;" : "=l"(r) : "l"(a), "l"(b), "l"(c)); return r;
}

// ============================================================================
// Fused pass AB: sigmoid + compaction once; term1 (dmin) and term2 partials.
// grid: (row=128, b=16), block: 128 threads
// ============================================================================
__global__ void __launch_bounds__(128) passAB_kernel(
    const float* __restrict__ hm, const int* __restrict__ ctr,
    const int* __restrict__ mask)
{
    const int row = blockIdx.x, b = blockIdx.y;
    const int tid = threadIdx.x;
    const int wid = tid >> 5, lid = tid & 31;

    __shared__ float4 spq[Wd];
    __shared__ float  spx[Kn], sdy2[Kn];
    __shared__ int    wcnt[4];
    __shared__ float  red[4][4];

    const float fy = (float)row, fx = (float)tid;

    // --- sigmoid for this row's cells (both s) ---
    const int base = b * HWn + row * Wd + tid;
    float h0 = hm[base];
    float h1 = hm[Bn * HWn + base];
    float p0 = 1.0f / (1.0f + __expf(-h0));
    float p1 = 1.0f / (1.0f + __expf(-h1));
    p0 = fminf(fmaxf(p0, 1e-4f), 1.0f - 1e-4f);
    p1 = fminf(fmaxf(p1, 1e-4f), 1.0f - 1e-4f);
    spq[tid] = make_float4(p0, p1, MPD - p0 * MAXD, MPD - p1 * MAXD);

    // --- compaction of valid points (thread = k) ---
    const int mk = mask[b * Kn + tid];
    unsigned bal = __ballot_sync(0xFFFFFFFFu, mk != 0);
    if (lid == 0) wcnt[wid] = __popc(bal);
    __syncthreads();
    int off = 0;
#pragma unroll
    for (int i = 0; i < 4; i++) if (i < wid) off += wcnt[i];
    const int V = wcnt[0] + wcnt[1] + wcnt[2] + wcnt[3];
    if (mk) {
        int slot = off + __popc(bal & ((1u << lid) - 1u));
        // pts = ctr[..., ::-1] : py = ctr[...,1], px = ctr[...,0]
        float pxk = (float)ctr[(b * Kn + tid) * 2 + 0];
        float pyk = (float)ctr[(b * Kn + tid) * 2 + 1];
        spx[slot] = pxk;
        float dyv = fy - pyk;
        sdy2[slot] = dyv * dyv;
    }
    __syncthreads();

    // ---------------- term1: dmin per cell + row reduce ----------------
    float mind = MAXD2;
#pragma unroll 4
    for (int j = 0; j < V; j++) {
        float dxv = fx - spx[j];
        mind = fminf(mind, fmaf(dxv, dxv, sdy2[j]));
    }
    float dmin = sqrt_ap(mind);

    float v0 = p0 * dmin, v1 = p1 * dmin, v2 = p0, v3 = p1;
#pragma unroll
    for (int o = 16; o > 0; o >>= 1) {
        v0 += __shfl_down_sync(0xFFFFFFFFu, v0, o);
        v1 += __shfl_down_sync(0xFFFFFFFFu, v1, o);
        v2 += __shfl_down_sync(0xFFFFFFFFu, v2, o);
        v3 += __shfl_down_sync(0xFFFFFFFFu, v3, o);
    }
    if (lid == 0) { red[wid][0] = v0; red[wid][1] = v1; red[wid][2] = v2; red[wid][3] = v3; }
    __syncthreads();
    if (tid == 0) {
        float4 o4;
        o4.x = red[0][0] + red[1][0] + red[2][0] + red[3][0];
        o4.y = red[0][1] + red[1][1] + red[2][1] + red[3][1];
        o4.z = red[0][2] + red[1][2] + red[2][2] + red[3][2];
        o4.w = red[0][3] + red[1][3] + red[2][3] + red[3][3];
        g_t1[b * Hd + row] = o4;
    }

    // ---------------- term2: heavy partials ----------------
    // work item = (valid slot, half-row); all 128 threads busy when V>=64
    for (int w = tid; w < 2 * Kn; w += 128) {
        const int slot = w >> 1, half = w & 1;
        ull acc = 0ULL;
        if (slot < V) {
            const float px = spx[slot];
            const float dy2 = sdy2[slot];
            const int xb = half << 6;
            const float u0 = (float)xb - px;
#pragma unroll 4
            for (int g = 0; g < 16; g++) {
                const float ug = u0 + (float)(g * 4);
                float P[4]; ull xv[4];
#pragma unroll
                for (int j = 0; j < 4; j++) {
                    float t = ug + (float)j;
                    float dsq = fmaf(t, t, dy2);
                    float d = sqrt_ap(dsq);
                    float4 pq = spq[xb + g * 4 + j];     // broadcast LDS.128
                    float x0 = fmaf(pq.x, d, pq.z);      // (1-p)M + p d + eps
                    float x1 = fmaf(pq.y, d, pq.w);
                    xv[j] = pk(x0, x1);
                    P[j] = x0 * x1;
                }
                // one rcp for 8 values
                float P01 = P[0] * P[1];
                float P23 = P[2] * P[3];
                float r = rcp_ap(P01 * P23);
                float r01 = r * P23;
                float r23 = r * P01;
                float qv[4];
                qv[0] = r01 * P[1];
                qv[1] = r01 * P[0];
                qv[2] = r23 * P[3];
                qv[3] = r23 * P[2];
#pragma unroll
                for (int j = 0; j < 4; j++) {
                    float x0, x1; upk(x0, x1, xv[j]);
                    float i0 = qv[j] * x1;
                    float i1 = qv[j] * x0;
                    ull iv = pk(i0, i1);
                    ull a = mul2(iv, iv);
                    a = mul2(a, a);
                    a = mul2(a, a);
                    acc = fma2(a, iv, acc);              // += x^-9
                }
            }
        }
        float a0, a1; upk(a0, a1, acc);
        const int rr = row * 2 + half;
        g_part2[((0 * Bn + b) * 256 + rr) * Kn + slot] = a0;
        g_part2[((1 * Bn + b) * 256 + rr) * Kn + slot] = a1;
    }
}

// ============================================================================
// Pass C1: reduce g_part2 over 256 row-halves -> minn per (s,b,slot)
// grid: 512 blocks x 256 threads; warp per (s,b,slot)
// ============================================================================
__global__ void __launch_bounds__(256) passC1_kernel(const int* __restrict__ mask)
{
    const int warpid = threadIdx.x >> 5, lane = threadIdx.x & 31;
    const int sb = blockIdx.x >> 4;
    const int b = sb & (Bn - 1);
    const int slot = ((blockIdx.x & 15) << 3) + warpid;

    __shared__ int wcnt[4];
    if (threadIdx.x < Kn) {
        int mk = mask[b * Kn + threadIdx.x];
        unsigned bal = __ballot_sync(0xFFFFFFFFu, mk != 0);
        if ((threadIdx.x & 31) == 0) wcnt[threadIdx.x >> 5] = __popc(bal);
    }
    __syncthreads();
    const int V = wcnt[0] + wcnt[1] + wcnt[2] + wcnt[3];

    float v = 0.0f;
    if (slot < V) {
        const float* bp = &g_part2[(sb * 256 + lane) * Kn + slot];
        float s = 0.0f;
#pragma unroll
        for (int t = 0; t < 8; t++) s += bp[t * 32 * Kn];
#pragma unroll
        for (int o = 16; o > 0; o >>= 1) s += __shfl_down_sync(0xFFFFFFFFu, s, o);
        if (lane == 0) v = powf(s * (1.0f / (float)HWn), -1.0f / 9.0f);
    }
    if (lane == 0) g_minn[sb * Kn + slot] = v;
}

// ============================================================================
// IoU kernel: grid 32 blocks (sb), 128 threads (k). Parallel scattered gathers.
// ============================================================================
__device__ __forceinline__ float smoothl(float l) {
    return (l < 0.2f) ? (2.5f * l * l) : (l - 0.1f);
}

__global__ void __launch_bounds__(128) passIoU_kernel(
    const float* __restrict__ wh_map, const float* __restrict__ reg_map,
    const float* __restrict__ reg_gt, const float* __restrict__ wh_gt,
    const int* __restrict__ ind, const int* __restrict__ mask)
{
    const int sb = blockIdx.x;
    const int b = sb & (Bn - 1);
    const int k = threadIdx.x;
    const int wid = k >> 5, lid = k & 31;

    __shared__ float wred[4];
    __shared__ int   wv[4];

    const int mk = mask[b * Kn + k];
    unsigned bal = __ballot_sync(0xFFFFFFFFu, mk != 0);

    float v = 0.0f;
    if (mk) {
        int id = ind[b * Kn + k];
        float R0 = reg_map[(sb * 2 + 0) * HWn + id];
        float R1 = reg_map[(sb * 2 + 1) * HWn + id];
        float W0 = wh_map[(sb * 2 + 0) * HWn + id];
        float W1 = wh_map[(sb * 2 + 1) * HWn + id];
        float g0 = reg_gt[(b * Kn + k) * 2 + 0];
        float g1 = reg_gt[(b * Kn + k) * 2 + 1];
        float wg = wh_gt[(b * Kn + k) * 2 + 0];
        float hg = wh_gt[(b * Kn + k) * 2 + 1];
        float adx = fabsf(g0 - R0);
        float ady = fabsf(g1 - R1);
        float ldx = 1.0f - fmaxf((wg - 2.0f * adx) / (wg + 2.0f * adx + EPSf), 0.0f);
        float ldy = 1.0f - fmaxf((hg - 2.0f * ady) / (hg + 2.0f * ady + EPSf), 0.0f);
        float ldw = 1.0f - fminf(wg / (W0 + EPSf), W0 / (wg + EPSf));
        float ldh = 1.0f - fminf(hg / (W1 + EPSf), W1 / (hg + EPSf));
        v = smoothl(ldx) + smoothl(ldy) + smoothl(ldw) + smoothl(ldh);
    }
#pragma unroll
    for (int o = 16; o > 0; o >>= 1) v += __shfl_down_sync(0xFFFFFFFFu, v, o);
    if (lid == 0) { wred[wid] = v; wv[wid] = __popc(bal); }
    __syncthreads();
    if (k == 0) {
        g_iou[sb] = wred[0] + wred[1] + wred[2] + wred[3];
        if (sb < Bn) g_msum[sb] = wv[0] + wv[1] + wv[2] + wv[3];
    }
}

// ============================================================================
// Finalize: 1 block x 1024 threads, warp per (s,b). All lane-parallel.
// ============================================================================
__global__ void __launch_bounds__(1024) passFin_kernel(
    float* __restrict__ out, int out_size)
{
    const int tid = threadIdx.x;
    const int sb = tid >> 5, lane = tid & 31;
    const int b = sb & (Bn - 1);
    const int s = sb >> 4;

    __shared__ float sterm_hm[Sn * Bn], sterm_iou[Sn * Bn];

    // t2: sum of minn over slots (4 per lane)
    float t2s = 0.0f;
#pragma unroll
    for (int t = 0; t < 4; t++) t2s += g_minn[sb * Kn + lane + t * 32];

    // t1: sum g_t1 rows (4 per lane)
    float num = 0.0f, den = 0.0f;
#pragma unroll
    for (int t = 0; t < 4; t++) {
        float4 v = g_t1[b * Hd + lane + t * 32];
        num += (s == 0) ? v.x : v.y;
        den += (s == 0) ? v.z : v.w;
    }
#pragma unroll
    for (int o = 16; o > 0; o >>= 1) {
        t2s += __shfl_down_sync(0xFFFFFFFFu, t2s, o);
        num += __shfl_down_sync(0xFFFFFFFFu, num, o);
        den += __shfl_down_sync(0xFFFFFFFFu, den, o);
    }
    if (lane == 0) {
        int ms = g_msum[b];
        float validb = (ms > 0) ? 1.0f : 0.0f;
        float fm = fmaxf((float)ms, 1.0f);
        float t1 = num / (den + EPSf);
        sterm_hm[sb] = (t1 + t2s / fm) * validb;
        sterm_iou[sb] = (g_iou[sb] / (fm * 4.0f)) * validb;
    }
    __syncthreads();

    if (tid == 0) {
        float hm_loss = 0.0f, iou_loss = 0.0f;
        for (int i = 0; i < Sn * Bn; i++) { hm_loss += sterm_hm[i]; iou_loss += sterm_iou[i]; }
        hm_loss *= (1.0f / (float)(Sn * Bn));
        iou_loss *= (1.0f / (float)(Sn * Bn));
        float loss = 1.0f * hm_loss + 0.1f * iou_loss;
        out[0] = loss;
        if (out_size > 1) out[1] = hm_loss;
        if (out_size > 2) out[2] = iou_loss;
    }
}

// ============================================================================
extern "C" void kernel_launch(void* const* d_in, const int* in_sizes, int n_in,
                              void* d_out, int out_size)
{
    const float* hm      = (const float*)d_in[0];
    const float* wh_map  = (const float*)d_in[1];
    const float* reg_map = (const float*)d_in[2];
    const float* reg_gt  = (const float*)d_in[3];
    const float* wh_gt   = (const float*)d_in[4];
    const int*   ind     = (const int*)d_in[5];
    const int*   ctr     = (const int*)d_in[6];
    const int*   mask    = (const int*)d_in[7];
    float* out = (float*)d_out;

    dim3 grid(Hd, Bn);
    passAB_kernel<<<grid, 128>>>(hm, ctr, mask);
    passC1_kernel<<<512, 256>>>(mask);
    passIoU_kernel<<<Sn * Bn, 128>>>(wh_map, reg_map, reg_gt, wh_gt, ind, mask);
    passFin_kernel<<<1, 1024>>>(out, out_size);
}

// round 6
// speedup vs baseline: 6.2183x; 1.0692x over previous
#include <cuda_runtime.h>
#include <cstdint>

#define Sn 2
#define Bn 16
#define Kn 128
#define Hd 128
#define Wd 128
#define HWn (Hd*Wd)

#define EPSf 1e-6f
#define MAXD 181.01933598375618f
#define MAXD2 32768.0f
#define MPD (MAXD + EPSf)

#define C1_BLOCKS 512
#define IOU_BLOCKS 32
#define TOT_BLOCKS (C1_BLOCKS + IOU_BLOCKS)

typedef unsigned long long ull;

// ---- device scratch ----
static __device__ float4 g_t1[Bn * Hd];                    // per (b,row): {sum p0*dmin, sum p1*dmin, sum p0, sum p1}
static __device__ float  g_part2[Bn * Kn * 256 * 2];       // ((b*Kn+slot)*256 + rowhalf)*2 + s
static __device__ float  g_minn[Sn * Bn * Kn];             // per (s,b,slot)
static __device__ float  g_iou[Sn * Bn];                   // per (s,b)
static __device__ int    g_msum[Bn];                       // per b: valid count
static __device__ int    g_done;                           // completion counter (reset each run)

__device__ __forceinline__ float sqrt_ap(float x) {
    float r; asm("sqrt.approx.f32 %0, %1;" : "=f"(r) : "f"(x)); return r;
}
__device__ __forceinline__ float rcp_ap(float x) {
    float r; asm("rcp.approx.f32 %0, %1;" : "=f"(r) : "f"(x)); return r;
}
__device__ __forceinline__ ull pk(float lo, float hi) {
    ull r; asm("mov.b64 %0, {%1, %2};" : "=l"(r) : "f"(lo), "f"(hi)); return r;
}
__device__ __forceinline__ void upk(float& lo, float& hi, ull v) {
    asm("mov.b64 {%0, %1}, %2;" : "=f"(lo), "=f"(hi) : "l"(v));
}
__device__ __forceinline__ ull mul2(ull a, ull b) {
    ull r; asm("mul.rn.f32x2 %0, %1, %2;" : "=l"(r) : "l"(a), "l"(b)); return r;
}
__device__ __forceinline__ ull fma2(ull a, ull b, ull c) {
    ull r; asm("fma.rn.f32x2 %0, %1, %2, %3;" : "=l"(r) : "l"(a), "l"(b), "l"(c)); return r;
}

// ============================================================================
// Kernel 1 — fused pass AB: sigmoid + compaction; term1 (dmin) + term2 partials
// grid: (row=128, b=16), block: 128 threads
// ============================================================================
__global__ void __launch_bounds__(128) passAB_kernel(
    const float* __restrict__ hm, const int* __restrict__ ctr,
    const int* __restrict__ mask)
{
    const int row = blockIdx.x, b = blockIdx.y;
    const int tid = threadIdx.x;
    const int wid = tid >> 5, lid = tid & 31;

    __shared__ float4 spq[Wd];
    __shared__ float  spx[Kn], sdy2[Kn];
    __shared__ int    wcnt[4];
    __shared__ float  red[4][4];

    const float fy = (float)row, fx = (float)tid;

    // --- sigmoid for this row's cells (both s) ---
    const int base = b * HWn + row * Wd + tid;
    float h0 = hm[base];
    float h1 = hm[Bn * HWn + base];
    float p0 = 1.0f / (1.0f + __expf(-h0));
    float p1 = 1.0f / (1.0f + __expf(-h1));
    p0 = fminf(fmaxf(p0, 1e-4f), 1.0f - 1e-4f);
    p1 = fminf(fmaxf(p1, 1e-4f), 1.0f - 1e-4f);
    spq[tid] = make_float4(p0, p1, MPD - p0 * MAXD, MPD - p1 * MAXD);

    // --- compaction of valid points (thread = k) ---
    const int mk = mask[b * Kn + tid];
    unsigned bal = __ballot_sync(0xFFFFFFFFu, mk != 0);
    if (lid == 0) wcnt[wid] = __popc(bal);
    __syncthreads();
    int off = 0;
#pragma unroll
    for (int i = 0; i < 4; i++) if (i < wid) off += wcnt[i];
    const int V = wcnt[0] + wcnt[1] + wcnt[2] + wcnt[3];
    if (mk) {
        int slot = off + __popc(bal & ((1u << lid) - 1u));
        float pxk = (float)ctr[(b * Kn + tid) * 2 + 0];
        float pyk = (float)ctr[(b * Kn + tid) * 2 + 1];
        spx[slot] = pxk;
        float dyv = fy - pyk;
        sdy2[slot] = dyv * dyv;
    }
    __syncthreads();

    // ---------------- term1: dmin per cell + row reduce ----------------
    float mind = MAXD2;
#pragma unroll 4
    for (int j = 0; j < V; j++) {
        float dxv = fx - spx[j];
        mind = fminf(mind, fmaf(dxv, dxv, sdy2[j]));
    }
    float dmin = sqrt_ap(mind);

    float v0 = p0 * dmin, v1 = p1 * dmin, v2 = p0, v3 = p1;
#pragma unroll
    for (int o = 16; o > 0; o >>= 1) {
        v0 += __shfl_down_sync(0xFFFFFFFFu, v0, o);
        v1 += __shfl_down_sync(0xFFFFFFFFu, v1, o);
        v2 += __shfl_down_sync(0xFFFFFFFFu, v2, o);
        v3 += __shfl_down_sync(0xFFFFFFFFu, v3, o);
    }
    if (lid == 0) { red[wid][0] = v0; red[wid][1] = v1; red[wid][2] = v2; red[wid][3] = v3; }
    __syncthreads();
    if (tid == 0) {
        float4 o4;
        o4.x = red[0][0] + red[1][0] + red[2][0] + red[3][0];
        o4.y = red[0][1] + red[1][1] + red[2][1] + red[3][1];
        o4.z = red[0][2] + red[1][2] + red[2][2] + red[3][2];
        o4.w = red[0][3] + red[1][3] + red[2][3] + red[3][3];
        g_t1[b * Hd + row] = o4;
    }

    // ---------------- term2: heavy partials ----------------
    for (int w = tid; w < 2 * Kn; w += 128) {
        const int slot = w >> 1, half = w & 1;
        ull acc = 0ULL;
        if (slot < V) {
            const float px = spx[slot];
            const float dy2 = sdy2[slot];
            const int xb = half << 6;
            const float u0 = (float)xb - px;
#pragma unroll 4
            for (int g = 0; g < 16; g++) {
                const float ug = u0 + (float)(g * 4);
                float P[4]; ull xv[4];
#pragma unroll
                for (int j = 0; j < 4; j++) {
                    float t = ug + (float)j;
                    float dsq = fmaf(t, t, dy2);
                    float d = sqrt_ap(dsq);
                    float4 pq = spq[xb + g * 4 + j];       // broadcast LDS.128
                    ull pv = pk(pq.x, pq.y);
                    ull qc = pk(pq.z, pq.w);
                    ull dd = pk(d, d);
                    xv[j] = fma2(pv, dd, qc);              // {x0, x1} = p*d + q
                    float x0, x1; upk(x0, x1, xv[j]);
                    P[j] = x0 * x1;
                }
                // one rcp for 8 values
                float P01 = P[0] * P[1];
                float P23 = P[2] * P[3];
                float r = rcp_ap(P01 * P23);
                float r01 = r * P23;
                float r23 = r * P01;
                float qv[4];
                qv[0] = r01 * P[1];
                qv[1] = r01 * P[0];
                qv[2] = r23 * P[3];
                qv[3] = r23 * P[2];
#pragma unroll
                for (int j = 0; j < 4; j++) {
                    float x0, x1; upk(x0, x1, xv[j]);
                    float i0 = qv[j] * x1;
                    float i1 = qv[j] * x0;
                    ull iv = pk(i0, i1);
                    ull a = mul2(iv, iv);
                    a = mul2(a, a);
                    a = mul2(a, a);
                    acc = fma2(a, iv, acc);                // += x^-9
                }
            }
        }
        float a0, a1; upk(a0, a1, acc);
        const int rr = row * 2 + half;
        // interleaved (s0,s1) layout, rowhalf innermost -> coalesced C1 reads
        *(float2*)&g_part2[((b * Kn + slot) * 256 + rr) * 2] = make_float2(a0, a1);
    }
}

// ============================================================================
// Kernel 2 — fused C1 reduction + IoU + (last block) finalize
// grid: 544 blocks x 256 threads
//   blocks [0,512): warp per (s,b,slot): reduce g_part2 -> g_minn
//   blocks [512,544): per (s,b) bounded IoU gathers -> g_iou, g_msum
//   last block to finish: finalize -> out
// ============================================================================
__device__ __forceinline__ float smoothl(float l) {
    return (l < 0.2f) ? (2.5f * l * l) : (l - 0.1f);
}

__global__ void __launch_bounds__(256) passC_kernel(
    const float* __restrict__ wh_map, const float* __restrict__ reg_map,
    const float* __restrict__ reg_gt, const float* __restrict__ wh_gt,
    const int* __restrict__ ind, const int* __restrict__ mask,
    float* __restrict__ out, int out_size)
{
    const int bid = blockIdx.x;
    const int tid = threadIdx.x;
    const int warpid = tid >> 5, lane = tid & 31;

    __shared__ int   wcnt[4];
    __shared__ float wred[4];
    __shared__ int   wv[4];
    __shared__ int   slast;

    if (bid < C1_BLOCKS) {
        // ---- C1: reduce over 256 row-halves ----
        const int sb = bid >> 4;                 // 0..31
        const int s = sb >> 4, b = sb & (Bn - 1);
        const int slot = ((bid & 15) << 3) + warpid;

        if (tid < Kn) {
            int mk = mask[b * Kn + tid];
            unsigned bal = __ballot_sync(0xFFFFFFFFu, mk != 0);
            if ((tid & 31) == 0) wcnt[tid >> 5] = __popc(bal);
        }
        __syncthreads();
        const int V = wcnt[0] + wcnt[1] + wcnt[2] + wcnt[3];

        float v = 0.0f;
        if (slot < V) {
            const float* bp = &g_part2[((b * Kn + slot) * 256) * 2 + s];
            float ssum = 0.0f;
#pragma unroll
            for (int t = 0; t < 8; t++) ssum += bp[(lane + t * 32) * 2];
#pragma unroll
            for (int o = 16; o > 0; o >>= 1) ssum += __shfl_down_sync(0xFFFFFFFFu, ssum, o);
            if (lane == 0)
                v = powf(ssum * (1.0f / (float)HWn), -1.0f / 9.0f);
        }
        if (lane == 0) g_minn[sb * Kn + slot] = v;
    } else {
        // ---- IoU: per (s,b), thread = k (first 128 threads) ----
        const int sb = bid - C1_BLOCKS;
        const int b = sb & (Bn - 1);
        if (tid < Kn) {
            const int k = tid;
            const int mk = mask[b * Kn + k];
            unsigned bal = __ballot_sync(0xFFFFFFFFu, mk != 0);
            float v = 0.0f;
            if (mk) {
                int id = ind[b * Kn + k];
                float R0 = reg_map[(sb * 2 + 0) * HWn + id];
                float R1 = reg_map[(sb * 2 + 1) * HWn + id];
                float W0 = wh_map[(sb * 2 + 0) * HWn + id];
                float W1 = wh_map[(sb * 2 + 1) * HWn + id];
                float g0 = reg_gt[(b * Kn + k) * 2 + 0];
                float g1 = reg_gt[(b * Kn + k) * 2 + 1];
                float wg = wh_gt[(b * Kn + k) * 2 + 0];
                float hg = wh_gt[(b * Kn + k) * 2 + 1];
                float adx = fabsf(g0 - R0);
                float ady = fabsf(g1 - R1);
                float ldx = 1.0f - fmaxf((wg - 2.0f * adx) / (wg + 2.0f * adx + EPSf), 0.0f);
                float ldy = 1.0f - fmaxf((hg - 2.0f * ady) / (hg + 2.0f * ady + EPSf), 0.0f);
                float ldw = 1.0f - fminf(wg / (W0 + EPSf), W0 / (wg + EPSf));
                float ldh = 1.0f - fminf(hg / (W1 + EPSf), W1 / (hg + EPSf));
                v = smoothl(ldx) + smoothl(ldy) + smoothl(ldw) + smoothl(ldh);
            }
#pragma unroll
            for (int o = 16; o > 0; o >>= 1) v += __shfl_down_sync(0xFFFFFFFFu, v, o);
            if ((tid & 31) == 0) { wred[tid >> 5] = v; wv[tid >> 5] = __popc(bal); }
        }
        __syncthreads();
        if (tid == 0) {
            g_iou[sb] = wred[0] + wred[1] + wred[2] + wred[3];
            if (sb < Bn) g_msum[sb] = wv[0] + wv[1] + wv[2] + wv[3];
        }
    }

    // ---- completion protocol (threadFenceReduction pattern) ----
    __threadfence();
    __syncthreads();
    if (tid == 0) {
        int prev = atomicAdd(&g_done, 1);
        slast = (prev == TOT_BLOCKS - 1) ? 1 : 0;
        if (slast) g_done = 0;                   // reset for next graph replay
    }
    __syncthreads();

    if (slast) {
        __threadfence();
        __shared__ float sterm_hm[Sn * Bn], sterm_iou[Sn * Bn];
        // warp per sb, 8 warps x 4 iterations
        for (int sb2 = warpid; sb2 < Sn * Bn; sb2 += 8) {
            const int b = sb2 & (Bn - 1);
            const int s = sb2 >> 4;
            float t2s = 0.0f, num = 0.0f, den = 0.0f;
#pragma unroll
            for (int t = 0; t < 4; t++) {
                t2s += g_minn[sb2 * Kn + lane + t * 32];
                float4 v = g_t1[b * Hd + lane + t * 32];
                num += (s == 0) ? v.x : v.y;
                den += (s == 0) ? v.z : v.w;
            }
#pragma unroll
            for (int o = 16; o > 0; o >>= 1) {
                t2s += __shfl_down_sync(0xFFFFFFFFu, t2s, o);
                num += __shfl_down_sync(0xFFFFFFFFu, num, o);
                den += __shfl_down_sync(0xFFFFFFFFu, den, o);
            }
            if (lane == 0) {
                int ms = g_msum[b];
                float validb = (ms > 0) ? 1.0f : 0.0f;
                float fm = fmaxf((float)ms, 1.0f);
                float t1 = num / (den + EPSf);
                sterm_hm[sb2] = (t1 + t2s / fm) * validb;
                sterm_iou[sb2] = (g_iou[sb2] / (fm * 4.0f)) * validb;
            }
        }
        __syncthreads();
        if (tid == 0) {
            float hm_loss = 0.0f, iou_loss = 0.0f;
            for (int i = 0; i < Sn * Bn; i++) { hm_loss += sterm_hm[i]; iou_loss += sterm_iou[i]; }
            hm_loss *= (1.0f / (float)(Sn * Bn));
            iou_loss *= (1.0f / (float)(Sn * Bn));
            float loss = 1.0f * hm_loss + 0.1f * iou_loss;
            out[0] = loss;
            if (out_size > 1) out[1] = hm_loss;
            if (out_size > 2) out[2] = iou_loss;
        }
    }
}

// ============================================================================
extern "C" void kernel_launch(void* const* d_in, const int* in_sizes, int n_in,
                              void* d_out, int out_size)
{
    const float* hm      = (const float*)d_in[0];
    const float* wh_map  = (const float*)d_in[1];
    const float* reg_map = (const float*)d_in[2];
    const float* reg_gt  = (const float*)d_in[3];
    const float* wh_gt   = (const float*)d_in[4];
    const int*   ind     = (const int*)d_in[5];
    const int*   ctr     = (const int*)d_in[6];
    const int*   mask    = (const int*)d_in[7];
    float* out = (float*)d_out;

    dim3 grid(Hd, Bn);
    passAB_kernel<<<grid, 128>>>(hm, ctr, mask);
    passC_kernel<<<TOT_BLOCKS, 256>>>(wh_map, reg_map, reg_gt, wh_gt, ind, mask, out, out_size);
}